// round 8
// baseline (speedup 1.0000x reference)
#include <cuda_runtime.h>
#include <cuda_bf16.h>
#include <cstdint>

// ---------------- Problem dims ----------------
#define M_REAL 200            // T*C rows
#define M_PAD 256             // padded to 16 m16 tiles
#define KK 16384              // H*W
#define NN 8192               // D
#define DTILE 64              // d columns per CTA
#define K_CHUNK 128
#define NCH (KK / K_CHUNK)    // 128 chunks
#define NTHREADS 256

// ---------------- smem layout (bytes) ----------------
// A buffer: 512 rows (2 limbs x 256 m) x 144 B (128 s8 + 16 pad) = 73728
// B buffer: 64 d-rows x 144 B (128 s8 + pad)                     = 9216
// B fp32 staging: 128 k x 64 d x 4 B                             = 32768
#define APITCH 144
#define SMA_BUF (512 * 144)               // 73728
#define SMB_BUF (64 * 144)                // 9216
#define SM_A 0
#define SM_B (2 * SMA_BUF)                // 147456
#define SM_STG (SM_B + 2 * SMB_BUF)       // 165888
#define SMEM_TOTAL (SM_STG + 32768)       // 198656

// ---------------- device scratch (no runtime allocation) ----------------
__device__ signed char g_Ahi[M_PAD * KK];   // 4 MB
__device__ signed char g_Alo[M_PAD * KK];   // 4 MB

// ---------------- kernel 1: hist fp32 -> 14-bit fixed point, split s8 hi/lo ----------------
__global__ void st_convert(const float* __restrict__ hist) {
    int idx = blockIdx.x * blockDim.x + threadIdx.x;   // 0 .. M_PAD*KK/4-1
    int base = idx << 2;
    char4 hi, lo;
    if (idx < (M_REAL * KK) / 4) {
        float4 h = *(const float4*)(hist + base);
        int v0 = min(16383, __float2int_rn(h.x * 16384.0f));
        int v1 = min(16383, __float2int_rn(h.y * 16384.0f));
        int v2 = min(16383, __float2int_rn(h.z * 16384.0f));
        int v3 = min(16383, __float2int_rn(h.w * 16384.0f));
        hi = make_char4((char)(v0 >> 7), (char)(v1 >> 7), (char)(v2 >> 7), (char)(v3 >> 7));
        lo = make_char4((char)(v0 & 127), (char)(v1 & 127), (char)(v2 & 127), (char)(v3 & 127));
    } else {
        hi = make_char4(0, 0, 0, 0);
        lo = make_char4(0, 0, 0, 0);
    }
    *(char4*)(g_Ahi + base) = hi;
    *(char4*)(g_Alo + base) = lo;
}

// ---------------- IMMA helper ----------------
static __device__ __forceinline__ void imma(int* c, uint32_t a0, uint32_t a1, uint32_t a2,
                                            uint32_t a3, uint32_t b0, uint32_t b1) {
    asm volatile(
        "mma.sync.aligned.m16n8k32.row.col.s32.s8.s8.s32 "
        "{%0,%1,%2,%3}, {%4,%5,%6,%7}, {%8,%9}, {%0,%1,%2,%3};"
        : "+r"(c[0]), "+r"(c[1]), "+r"(c[2]), "+r"(c[3])
        : "r"(a0), "r"(a1), "r"(a2), "r"(a3), "r"(b0), "r"(b1));
}

static __device__ __forceinline__ uint32_t lds32(uint32_t addr) {
    uint32_t v;
    asm volatile("ld.shared.b32 %0, [%1];" : "=r"(v) : "r"(addr));
    return v;
}

// ---------------- kernel 2: s8 IMMA GEMM + fused sign epilogue ----------------
__global__ void __launch_bounds__(NTHREADS, 1)
st_gemm(const float* __restrict__ pos_w,
        const float* __restrict__ time_w,
        const float* __restrict__ pol_w,
        float* __restrict__ out)
{
    extern __shared__ char smem[];
    const uint32_t sbase = (uint32_t)__cvta_generic_to_shared(smem);
    const int tid = threadIdx.x;
    const int w = tid >> 5;
    const int lane = tid & 31;
    const int g = lane >> 2;          // group 0..7
    const int t = lane & 3;           // thread-in-group 0..3
    const int d0 = blockIdx.x * DTILE;

    int acc[2][2][8][4];              // [limb][mt][nf][c]
    #pragma unroll
    for (int l = 0; l < 2; l++)
        #pragma unroll
        for (int mt = 0; mt < 2; mt++)
            #pragma unroll
            for (int nf = 0; nf < 8; nf++)
                #pragma unroll
                for (int cc = 0; cc < 4; cc++) acc[l][mt][nf][cc] = 0;

    // ---- async loaders ----
    auto load_async = [&](int c, int buf) {
        const int kb = c * K_CHUNK;
        // A: 512 rows x 128 s8 -> pitch-144 smem
        {
            uint32_t abase = sbase + SM_A + (uint32_t)buf * SMA_BUF;
            const int unit = tid & 7, r0 = tid >> 3;
            #pragma unroll
            for (int i = 0; i < 16; i++) {
                int r = r0 + i * 32;               // 0..511
                int limb = r >> 8, m = r & 255;
                const signed char* src = (limb ? g_Alo : g_Ahi) + (size_t)m * KK + kb + unit * 16;
                uint32_t dst = abase + (uint32_t)(r * APITCH + unit * 16);
                asm volatile("cp.async.cg.shared.global [%0], [%1], 16;"
                             :: "r"(dst), "l"(src) : "memory");
            }
        }
        // B staging: 128 k-rows x 64 d fp32 (pitch 256 B)
        {
            uint32_t stg = sbase + SM_STG;
            const int du = tid & 15, kr = tid >> 4;
            #pragma unroll
            for (int i = 0; i < 8; i++) {
                int k = kr + i * 16;
                const float* src = pos_w + (size_t)(kb + k) * NN + d0 + du * 4;
                uint32_t dst = stg + (uint32_t)(k * 256 + du * 16);
                asm volatile("cp.async.cg.shared.global [%0], [%1], 16;"
                             :: "r"(dst), "l"(src) : "memory");
            }
        }
        asm volatile("cp.async.commit_group;" ::: "memory");
    };

    // fp32 staging -> s8 sign tile [d][k], pitch 144 B
    auto convertB = [&](int buf) {
        const float* stg = (const float*)(smem + SM_STG);
        char* smB = smem + SM_B + buf * SMB_BUF;
        const int d = tid & 63, kh = tid >> 6;
        #pragma unroll
        for (int j = 0; j < 8; j++) {
            int k = kh * 32 + j * 4;
            int i0 = __float2int_rn(stg[(k + 0) * 64 + d]);
            int i1 = __float2int_rn(stg[(k + 1) * 64 + d]);
            int i2 = __float2int_rn(stg[(k + 2) * 64 + d]);
            int i3 = __float2int_rn(stg[(k + 3) * 64 + d]);
            uint32_t p = (uint32_t)(i0 & 255) | ((uint32_t)(i1 & 255) << 8) |
                         ((uint32_t)(i2 & 255) << 16) | ((uint32_t)(i3 & 255) << 24);
            *(uint32_t*)(smB + d * APITCH + k) = p;
        }
    };

    auto compute = [&](int buf) {
        const uint32_t abase = sbase + SM_A + (uint32_t)buf * SMA_BUF;
        const uint32_t bbase = sbase + SM_B + (uint32_t)buf * SMB_BUF;
        #pragma unroll
        for (int kt = 0; kt < 4; kt++) {
            uint32_t b[8][2];
            #pragma unroll
            for (int nf = 0; nf < 8; nf++) {
                uint32_t ba = bbase + (uint32_t)((nf * 8 + g) * APITCH + kt * 32 + t * 4);
                b[nf][0] = lds32(ba);
                b[nf][1] = lds32(ba + 16);
            }
            #pragma unroll
            for (int limb = 0; limb < 2; limb++) {
                #pragma unroll
                for (int mt = 0; mt < 2; mt++) {
                    int row = limb * 256 + w * 32 + mt * 16 + g;
                    uint32_t aa = abase + (uint32_t)(row * APITCH + kt * 32 + t * 4);
                    uint32_t a0 = lds32(aa);
                    uint32_t a1 = lds32(aa + 8 * APITCH);
                    uint32_t a2 = lds32(aa + 16);
                    uint32_t a3 = lds32(aa + 8 * APITCH + 16);
                    #pragma unroll
                    for (int nf = 0; nf < 8; nf++)
                        imma(acc[limb][mt][nf], a0, a1, a2, a3, b[nf][0], b[nf][1]);
                }
            }
        }
    };

    // ---- pipelined mainloop ----
    load_async(0, 0);
    asm volatile("cp.async.wait_group 0;" ::: "memory");
    __syncthreads();
    convertB(0);
    __syncthreads();

    for (int c = 0; c < NCH; c++) {
        const int buf = c & 1;
        if (c + 1 < NCH) load_async(c + 1, buf ^ 1);
        compute(buf);
        if (c + 1 < NCH) {
            asm volatile("cp.async.wait_group 0;" ::: "memory");
            __syncthreads();
            convertB(buf ^ 1);
        }
        __syncthreads();
    }

    // ---- epilogue: combine limbs exactly in s32, C -> smem, weighted sign reduce ----
    float* smC = (float*)smem;   // 256 m x pitch 72 floats = 73728 B (reuse A region)
    #pragma unroll
    for (int mt = 0; mt < 2; mt++) {
        #pragma unroll
        for (int nf = 0; nf < 8; nf++) {
            int m = w * 32 + mt * 16 + g;
            int d = nf * 8 + t * 2;
            float2 v01, v23;
            v01.x = (float)(acc[0][mt][nf][0] * 128 + acc[1][mt][nf][0]);
            v01.y = (float)(acc[0][mt][nf][1] * 128 + acc[1][mt][nf][1]);
            v23.x = (float)(acc[0][mt][nf][2] * 128 + acc[1][mt][nf][2]);
            v23.y = (float)(acc[0][mt][nf][3] * 128 + acc[1][mt][nf][3]);
            *(float2*)(smC + m * 72 + d) = v01;
            *(float2*)(smC + (m + 8) * 72 + d) = v23;
        }
    }
    __syncthreads();

    {
        const int d = tid & 63, q = tid >> 6;
        const int mmax = (q == 3) ? 8 : 64;     // clip to M_REAL=200
        float s = 0.0f;
        for (int mi = 0; mi < mmax; mi++) {
            int m = q * 64 + mi;
            float wv = time_w[(size_t)(m >> 1) * NN + d0 + d] *
                       pol_w[(size_t)(m & 1) * NN + d0 + d];
            s += smC[m * 72 + d] * wv;
        }
        float* red = (float*)(smem + SM_STG);
        red[tid] = s;
        __syncthreads();
        if (tid < DTILE) {
            float v = red[tid] + red[tid + 64] + red[tid + 128] + red[tid + 192];
            out[d0 + tid] = (v > 0.0f) ? 1.0f : ((v < 0.0f) ? -1.0f : 0.0f);
        }
    }
}

// ---------------- launch ----------------
extern "C" void kernel_launch(void* const* d_in, const int* in_sizes, int n_in,
                              void* d_out, int out_size) {
    const float* hist   = (const float*)d_in[0];   // [100, 2, 128, 128]
    const float* time_w = (const float*)d_in[1];   // [100, 8192]
    const float* pol_w  = (const float*)d_in[2];   // [2, 8192]
    const float* pos_w  = (const float*)d_in[3];   // [16384, 8192]
    float* out = (float*)d_out;                    // [8192]

    cudaFuncSetAttribute(st_gemm, cudaFuncAttributeMaxDynamicSharedMemorySize, SMEM_TOTAL);

    st_convert<<<(M_PAD * KK / 4) / 256, 256>>>(hist);
    st_gemm<<<NN / DTILE, NTHREADS, SMEM_TOTAL>>>(pos_w, time_w, pol_w, out);
}

// round 9
// speedup vs baseline: 2.9515x; 2.9515x over previous
#include <cuda_runtime.h>
#include <cuda_bf16.h>
#include <cstdint>

// ---------------- Problem dims ----------------
#define M_REAL 200              // T*C rows
#define M_PAD 224               // padded to 14 m16 tiles per limb
#define AROWS (2 * M_PAD)       // 448 scratch rows (hi limb 0..223, lo 224..447)
#define KK 16384                // H*W
#define NN 8192                 // D
#define DTILE 64                // d columns per CTA
#define KCH 64                  // k per chunk
#define NCH (KK / KCH)          // 256 chunks
#define NDT (NN / DTILE)        // 128 CTAs

#define ABYTES (AROWS * 128)    // 57344 per chunk
#define BBYTES (DTILE * 128)    // 8192 per (chunk, dtile)
#define STAGEB (ABYTES + BBYTES)// 65536
#define NSTAGE 3

// smem layout
#define SM_MBAR (NSTAGE * STAGEB)        // 196608
#define SM_SG (SM_MBAR + NSTAGE * 8)     // 196632 -> align
#define SM_SG_AL 196640
#define SMEM_TOTAL (SM_SG_AL + 64 * 4)   // 196896

// ---------------- device scratch (static, no runtime allocation) ----------------
__device__ __nv_bfloat16 g_A[NCH * AROWS * 64];        // 14.7 MB, chunk-tiled
__device__ __nv_bfloat16 g_B[NCH * NDT * DTILE * 64];  // 256 MB, (chunk,dtile)-tiled

// ---------------- PTX helpers ----------------
#define MBAR_INIT(a, c) asm volatile("mbarrier.init.shared.b64 [%0], %1;" :: "r"(a), "r"(c) : "memory")
#define MBAR_EXPECT(a, n) asm volatile("mbarrier.arrive.expect_tx.shared.b64 _, [%0], %1;" :: "r"(a), "r"(n) : "memory")

static __device__ __forceinline__ void mbar_wait(uint32_t mbar, uint32_t parity) {
    asm volatile(
        "{\n\t.reg .pred P1;\n\t"
        "WAIT_LOOP_%=:\n\t"
        "mbarrier.try_wait.parity.acquire.cta.shared::cta.b64 P1, [%0], %1, 0x989680;\n\t"
        "@P1 bra.uni WAIT_DONE_%=;\n\t"
        "bra.uni WAIT_LOOP_%=;\n\t"
        "WAIT_DONE_%=:\n\t}"
        :: "r"(mbar), "r"(parity) : "memory");
}

static __device__ __forceinline__ void bulk_g2s(uint32_t dst, const void* src,
                                                uint32_t bytes, uint32_t mbar) {
    asm volatile(
        "cp.async.bulk.shared::cluster.global.mbarrier::complete_tx::bytes [%0], [%1], %2, [%3];"
        :: "r"(dst), "l"(src), "r"(bytes), "r"(mbar) : "memory");
}

static __device__ __forceinline__ void ldsm_x4(uint32_t* r, uint32_t addr) {
    asm volatile("ldmatrix.sync.aligned.m8n8.x4.shared.b16 {%0,%1,%2,%3}, [%4];"
                 : "=r"(r[0]), "=r"(r[1]), "=r"(r[2]), "=r"(r[3]) : "r"(addr));
}
static __device__ __forceinline__ void ldsm_x2t(uint32_t* r, uint32_t addr) {
    asm volatile("ldmatrix.sync.aligned.m8n8.x2.trans.shared.b16 {%0,%1}, [%2];"
                 : "=r"(r[0]), "=r"(r[1]) : "r"(addr));
}
static __device__ __forceinline__ void mma_bf16(float* c, const uint32_t* a, const uint32_t* b) {
    asm volatile(
        "mma.sync.aligned.m16n8k16.row.col.f32.bf16.bf16.f32 "
        "{%0,%1,%2,%3}, {%4,%5,%6,%7}, {%8,%9}, {%0,%1,%2,%3};"
        : "+f"(c[0]), "+f"(c[1]), "+f"(c[2]), "+f"(c[3])
        : "r"(a[0]), "r"(a[1]), "r"(a[2]), "r"(a[3]), "r"(b[0]), "r"(b[1]));
}

// ---------------- kernel 1: hist -> split bf16 hi/lo, chunk-tiled + swizzled ----------------
// thread handles (m 0..223, 16B-unit u 0..2047): 8 k-values
__global__ void convA(const float* __restrict__ hist) {
    int idx = blockIdx.x * blockDim.x + threadIdx.x;   // 458752 threads
    int m = idx >> 11;
    int u = idx & 2047;
    int kc = u >> 3, uu = u & 7;
    __nv_bfloat16 hi[8], lo[8];
    if (m < M_REAL) {
        const float* src = hist + (size_t)m * KK + u * 8;
        float4 f0 = *(const float4*)(src);
        float4 f1 = *(const float4*)(src + 4);
        float f[8] = {f0.x, f0.y, f0.z, f0.w, f1.x, f1.y, f1.z, f1.w};
        #pragma unroll
        for (int i = 0; i < 8; i++) {
            hi[i] = __float2bfloat16_rn(f[i]);
            lo[i] = __float2bfloat16_rn(f[i] - __bfloat162float(hi[i]));
        }
    } else {
        #pragma unroll
        for (int i = 0; i < 8; i++) { hi[i] = __float2bfloat16_rn(0.f); lo[i] = hi[i]; }
    }
    int sw = (uu ^ (m & 7)) * 16;   // byte offset of 16B unit within 128B row (swizzled)
    char* basep = (char*)g_A + (size_t)kc * (AROWS * 128);
    *(uint4*)(basep + m * 128 + sw) = *(uint4*)hi;
    *(uint4*)(basep + (M_PAD + m) * 128 + sw) = *(uint4*)lo;
}

// ---------------- kernel 2: pos_w fp32 -> bf16, (chunk,dtile)-tiled + swizzled ----------------
// thread handles (k, 16B-unit u 0..1023): 8 d-values
__global__ void convB(const float* __restrict__ pos_w) {
    int idx = blockIdx.x * blockDim.x + threadIdx.x;   // 16.78M threads
    int k = idx >> 10;
    int u = idx & 1023;
    int dt = u >> 3, du = u & 7;
    const float* src = pos_w + (size_t)k * NN + u * 8;
    float4 f0 = *(const float4*)(src);
    float4 f1 = *(const float4*)(src + 4);
    __nv_bfloat16 b[8];
    b[0] = __float2bfloat16_rn(f0.x); b[1] = __float2bfloat16_rn(f0.y);
    b[2] = __float2bfloat16_rn(f0.z); b[3] = __float2bfloat16_rn(f0.w);
    b[4] = __float2bfloat16_rn(f1.x); b[5] = __float2bfloat16_rn(f1.y);
    b[6] = __float2bfloat16_rn(f1.z); b[7] = __float2bfloat16_rn(f1.w);
    int sw = (du ^ (k & 7)) * 16;
    char* basep = (char*)g_B + ((size_t)(k >> 6) * NDT + dt) * BBYTES + (k & 63) * 128 + sw;
    *(uint4*)basep = *(uint4*)b;
}

// ---------------- kernel 3: bf16 m16n8k16 GEMM, bulk-copy pipeline, fused sign ----------------
__global__ void __launch_bounds__(256)
st_gemm(const float* __restrict__ time_w,
        const float* __restrict__ pol_w,
        float* __restrict__ out)
{
    extern __shared__ char smem[];
    const uint32_t sbase = (uint32_t)__cvta_generic_to_shared(smem);
    const int tid = threadIdx.x;
    const int w = tid >> 5, lane = tid & 31;
    const int g = lane >> 2, t = lane & 3;
    const int wm = w & 3, wn = w >> 2;       // 4 x 2 warp grid
    const int dt = blockIdx.x;
    float* sg = (float*)(smem + SM_SG_AL);

    if (tid < NSTAGE) MBAR_INIT(sbase + SM_MBAR + tid * 8, 1);
    if (tid < 64) sg[tid] = 0.0f;
    __syncthreads();

    // prefetch first NSTAGE chunks
    if (tid == 0) {
        #pragma unroll
        for (int s = 0; s < NSTAGE; s++) {
            uint32_t mb = sbase + SM_MBAR + s * 8;
            MBAR_EXPECT(mb, STAGEB);
            bulk_g2s(sbase + s * STAGEB,
                     (const char*)g_A + (size_t)s * ABYTES, ABYTES, mb);
            bulk_g2s(sbase + s * STAGEB + ABYTES,
                     (const char*)g_B + ((size_t)s * NDT + dt) * BBYTES, BBYTES, mb);
        }
    }

    float acc[7][4][4];
    #pragma unroll
    for (int i = 0; i < 7; i++)
        #pragma unroll
        for (int j = 0; j < 4; j++)
            #pragma unroll
            for (int cc = 0; cc < 4; cc++) acc[i][j][cc] = 0.0f;

    // per-lane ldmatrix address components
    const int Lr = lane & 15;                       // B: k-row within 16
    const int arow_l = (lane & 7) + ((lane >> 3) & 1) * 8;  // A: row within tile
    const int asel = lane >> 4;                     // A: k-unit select

    for (int c = 0; c < NCH; c++) {
        const int s = c % NSTAGE;
        const uint32_t base = sbase + s * STAGEB;
        mbar_wait(sbase + SM_MBAR + s * 8, (uint32_t)((c / NSTAGE) & 1));

        #pragma unroll
        for (int kt = 0; kt < 4; kt++) {
            uint32_t bfr[4][2];
            #pragma unroll
            for (int j = 0; j < 4; j++) {
                int nf = wn * 4 + j;
                int k = kt * 16 + Lr;
                uint32_t ad = base + ABYTES + (uint32_t)(k * 128 + ((nf ^ (k & 7)) << 4));
                ldsm_x2t(bfr[j], ad);
            }
            #pragma unroll
            for (int i = 0; i < 7; i++) {
                int r = (wm + 4 * i) * 16 + arow_l;
                int u = kt * 2 + asel;
                uint32_t ad = base + (uint32_t)(r * 128 + ((u ^ (r & 7)) << 4));
                uint32_t a[4];
                ldsm_x4(a, ad);
                #pragma unroll
                for (int j = 0; j < 4; j++)
                    mma_bf16(acc[i][j], a, bfr[j]);
            }
        }
        __syncthreads();
        if (tid == 0 && c + NSTAGE < NCH) {
            int kc = c + NSTAGE;
            uint32_t mb = sbase + SM_MBAR + s * 8;
            MBAR_EXPECT(mb, STAGEB);
            bulk_g2s(base, (const char*)g_A + (size_t)kc * ABYTES, ABYTES, mb);
            bulk_g2s(base + ABYTES,
                     (const char*)g_B + ((size_t)kc * NDT + dt) * BBYTES, BBYTES, mb);
        }
    }

    // ---- fused epilogue: sum_m C[m,d]*time*pol, reduce, sign ----
    {
        const int d0 = dt * DTILE;
        float colsum[4][2];
        #pragma unroll
        for (int j = 0; j < 4; j++) { colsum[j][0] = 0.f; colsum[j][1] = 0.f; }

        #pragma unroll
        for (int i = 0; i < 7; i++) {
            int tile = wm + 4 * i;
            int rg = tile * 16 + g;
            int rg8 = rg + 8;
            int m0 = (rg < M_PAD) ? rg : rg - M_PAD;
            int m1 = (rg8 < M_PAD) ? rg8 : rg8 - M_PAD;
            bool v0 = m0 < M_REAL, v1 = m1 < M_REAL;
            #pragma unroll
            for (int j = 0; j < 4; j++) {
                int d = d0 + (wn * 4 + j) * 8 + 2 * t;
                if (v0) {
                    float wa = time_w[(size_t)(m0 >> 1) * NN + d] * pol_w[(size_t)(m0 & 1) * NN + d];
                    float wb = time_w[(size_t)(m0 >> 1) * NN + d + 1] * pol_w[(size_t)(m0 & 1) * NN + d + 1];
                    colsum[j][0] += acc[i][j][0] * wa;
                    colsum[j][1] += acc[i][j][1] * wb;
                }
                if (v1) {
                    float wa = time_w[(size_t)(m1 >> 1) * NN + d] * pol_w[(size_t)(m1 & 1) * NN + d];
                    float wb = time_w[(size_t)(m1 >> 1) * NN + d + 1] * pol_w[(size_t)(m1 & 1) * NN + d + 1];
                    colsum[j][0] += acc[i][j][2] * wa;
                    colsum[j][1] += acc[i][j][3] * wb;
                }
            }
        }
        #pragma unroll
        for (int j = 0; j < 4; j++) {
            #pragma unroll
            for (int cx = 0; cx < 2; cx++) {
                float v = colsum[j][cx];
                v += __shfl_xor_sync(0xFFFFFFFFu, v, 4);
                v += __shfl_xor_sync(0xFFFFFFFFu, v, 8);
                v += __shfl_xor_sync(0xFFFFFFFFu, v, 16);
                if (g == 0)
                    atomicAdd(&sg[(wn * 4 + j) * 8 + 2 * t + cx], v);
            }
        }
    }
    __syncthreads();
    if (tid < 64) {
        float v = sg[tid];
        out[dt * DTILE + tid] = (v > 0.0f) ? 1.0f : ((v < 0.0f) ? -1.0f : 0.0f);
    }
}

// ---------------- launch ----------------
extern "C" void kernel_launch(void* const* d_in, const int* in_sizes, int n_in,
                              void* d_out, int out_size) {
    const float* hist   = (const float*)d_in[0];   // [100, 2, 128, 128]
    const float* time_w = (const float*)d_in[1];   // [100, 8192]
    const float* pol_w  = (const float*)d_in[2];   // [2, 8192]
    const float* pos_w  = (const float*)d_in[3];   // [16384, 8192]
    float* out = (float*)d_out;                    // [8192]

    cudaFuncSetAttribute(st_gemm, cudaFuncAttributeMaxDynamicSharedMemorySize, SMEM_TOTAL);

    convA<<<(M_PAD * 2048) / 256, 256>>>(hist);
    convB<<<(KK * 1024) / 256, 256>>>(pos_w);
    st_gemm<<<NDT, 256, SMEM_TOTAL>>>(time_w, pol_w, out);
}